// round 11
// baseline (speedup 1.0000x reference)
#include <cuda_runtime.h>
#include <math.h>

#define F_DIM   2048
#define N_DIM   10000
#define B_DIM   8
#define J_DIM   10
#define R_DIM   20
#define H1_DIM  200
#define H2_DIM  100
#define FCHUNKS 8
#define FCHUNK  256                 /* F_DIM / FCHUNKS */
#define NTILE   512                 /* n per CTA: 256 threads * 2 */
#define HVEC    (2 * R_DIM * J_DIM) /* 400 */

// Scratch (static device globals -- no allocation allowed)
__device__ float g_part[FCHUNKS * B_DIM * J_DIM * N_DIM]; // 25.6 MB partial sums
__device__ float g_h[B_DIM * HVEC];                       // [8][400] MLP input

__device__ __forceinline__ void fma2(unsigned long long &acc,
                                     unsigned long long a,
                                     unsigned long long b) {
    // packed 2x fp32 FMA (FFMA2) -- only reachable via PTX f32x2
    asm("fma.rn.f32x2 %0, %1, %2, %0;" : "+l"(acc) : "l"(a), "l"(b));
}

// ---------------------------------------------------------------------------
// Kernel 1: streaming skinny GEMM. Each thread: one b, 2 consecutive n,
// one F-chunk of 256. Accumulators: 10 j f32x2 pairs (20 regs).
// 256 threads/CTA, ~50 regs -> ~40 resident warps/SM; unroll 8 lets ptxas
// batch 8 LDG.64 per block -> deep MLP for DRAM latency hiding.
// ---------------------------------------------------------------------------
__global__ __launch_bounds__(256) void k_conv(const float* __restrict__ x,
                                              const float* __restrict__ conv_w) {
    __shared__ __align__(16) unsigned long long wsp[FCHUNK * J_DIM]; // 20 KB

    const int b     = blockIdx.y;
    const int fc    = blockIdx.z;
    const int fbase = fc * FCHUNK;

    // Cooperative weight load + splat: wsp[fl*10 + j] = {w[j][fbase+fl], same}
    for (int idx = threadIdx.x; idx < FCHUNK * J_DIM; idx += 256) {
        const int fl = idx / J_DIM, j = idx % J_DIM;
        const float w = conv_w[j * F_DIM + fbase + fl];
        float2 ww = make_float2(w, w);
        wsp[idx] = *reinterpret_cast<unsigned long long*>(&ww);
    }
    __syncthreads();

    const int n0 = blockIdx.x * NTILE + threadIdx.x * 2;
    if (n0 >= N_DIM) return;   // N_DIM even; no partial vectors

    unsigned long long acc[J_DIM];
#pragma unroll
    for (int i = 0; i < J_DIM; ++i) acc[i] = 0ull;

    const float* xp = x + (b * F_DIM + fbase) * N_DIM + n0;

#pragma unroll 8
    for (int fl = 0; fl < FCHUNK; ++fl) {
        const unsigned long long xv =
            *reinterpret_cast<const unsigned long long*>(xp); // 2 n's (LDG.64)
        xp += N_DIM;
        const ulonglong2* wp = reinterpret_cast<const ulonglong2*>(&wsp[fl * J_DIM]);
#pragma unroll
        for (int jj = 0; jj < 5; ++jj) {       // 2 j per LDS.128
            const ulonglong2 w2 = wp[jj];
            fma2(acc[2 * jj + 0], xv, w2.x);
            fma2(acc[2 * jj + 1], xv, w2.y);
        }
    }

    float* pout = g_part + (fc * B_DIM * J_DIM + b * J_DIM) * N_DIM + n0;
#pragma unroll
    for (int j = 0; j < J_DIM; ++j)
        *reinterpret_cast<unsigned long long*>(pout + j * N_DIM) = acc[j];
}

// ---------------------------------------------------------------------------
// Kernel 2: per (b,j) row. One pass sums partials into smem AND records each
// thread's local max & min (tournament leaves). Each extraction pass then
// only (a) reduces the 256 leaf entries with warp 0, (b) rescans the single
// victim thread's ~40 elements. Max phase removes with -INF (recording
// idx/val), restore, then min phase (initial lmin stays valid after exact
// restore). Bias added post-selection (uniform shift, selection-invariant).
// ---------------------------------------------------------------------------
__global__ __launch_bounds__(256) void k_minmax(const float* __restrict__ conv_b) {
    const int row = blockIdx.x;            // b*10 + j
    const int tid = threadIdx.x;
    __shared__ float vals[N_DIM];          // 40 KB
    __shared__ float lmax[256], lmin[256];
    __shared__ int   lamax[256], lamin[256];
    __shared__ int   s_victim;
    __shared__ int   rem_idx[R_DIM];
    __shared__ float rem_val[R_DIM];

    float lm = -INFINITY, ln = INFINITY;
    int   la = tid, li = tid;
    for (int n = tid; n < N_DIM; n += 256) {
        float s = 0.f;
#pragma unroll
        for (int fcc = 0; fcc < FCHUNKS; ++fcc)
            s += g_part[(fcc * B_DIM * J_DIM + row) * N_DIM + n];
        vals[n] = s;
        if (s > lm) { lm = s; la = n; }
        if (s < ln) { ln = s; li = n; }
    }
    lmax[tid] = lm; lamax[tid] = la;
    lmin[tid] = ln; lamin[tid] = li;
    __syncthreads();

    const int   lane = tid & 31;
    const int   j    = row % J_DIM;
    const float bias = conv_b[j];
    float* out = g_h + (row / J_DIM) * HVEC + j * (2 * R_DIM);

    // ---- Phase A: top-R descending ----
    for (int pass = 0; pass < R_DIM; ++pass) {
        if (tid < 32) {
            float m = -INFINITY; int owner = 0;
#pragma unroll
            for (int k = lane; k < 256; k += 32)
                if (lmax[k] > m) { m = lmax[k]; owner = k; }
#pragma unroll
            for (int off = 16; off > 0; off >>= 1) {
                float o  = __shfl_down_sync(0xffffffffu, m, off);
                int   oo = __shfl_down_sync(0xffffffffu, owner, off);
                if (o > m) { m = o; owner = oo; }
            }
            if (lane == 0) {
                const int idx = lamax[owner];
                out[pass]     = m + bias;      // pass-th largest, descending
                rem_idx[pass] = idx;
                rem_val[pass] = m;
                vals[idx]     = -INFINITY;
                s_victim      = owner;
            }
        }
        __syncthreads();
        if (tid == s_victim) {                 // refresh victim leaf only
            float m = -INFINITY; int a = tid;
            for (int n = tid; n < N_DIM; n += 256)
                if (vals[n] > m) { m = vals[n]; a = n; }
            lmax[tid] = m; lamax[tid] = a;
        }
        __syncthreads();
    }

    // exact restore of removed top values; initial lmin remains valid
    if (tid < R_DIM) vals[rem_idx[tid]] = rem_val[tid];
    __syncthreads();

    // ---- Phase B: bottom-R, k-th smallest -> position 2R-1-pass ----
    for (int pass = 0; pass < R_DIM; ++pass) {
        if (tid < 32) {
            float m = INFINITY; int owner = 0;
#pragma unroll
            for (int k = lane; k < 256; k += 32)
                if (lmin[k] < m) { m = lmin[k]; owner = k; }
#pragma unroll
            for (int off = 16; off > 0; off >>= 1) {
                float o  = __shfl_down_sync(0xffffffffu, m, off);
                int   oo = __shfl_down_sync(0xffffffffu, owner, off);
                if (o < m) { m = o; owner = oo; }
            }
            if (lane == 0) {
                const int idx = lamin[owner];
                out[2 * R_DIM - 1 - pass] = m + bias;
                vals[idx] = INFINITY;
                s_victim  = owner;
            }
        }
        __syncthreads();
        if (tid == s_victim) {
            float m = INFINITY; int a = tid;
            for (int n = tid; n < N_DIM; n += 256)
                if (vals[n] < m) { m = vals[n]; a = n; }
            lmin[tid] = m; lamin[tid] = a;
        }
        __syncthreads();
    }
}

// ---------------------------------------------------------------------------
// Kernel 3: tiny MLP, one CTA per batch row.
// ---------------------------------------------------------------------------
__device__ __forceinline__ float sigmoidf_(float z) {
    return 1.f / (1.f + expf(-z));
}

__global__ __launch_bounds__(256) void k_mlp(const float* __restrict__ w1,
                                             const float* __restrict__ b1,
                                             const float* __restrict__ w2,
                                             const float* __restrict__ b2,
                                             const float* __restrict__ w3,
                                             const float* __restrict__ b3,
                                             float* __restrict__ out) {
    const int b   = blockIdx.x;
    const int tid = threadIdx.x;
    __shared__ float s0[HVEC], s1[H1_DIM], s2[H2_DIM];

    for (int i = tid; i < HVEC; i += 256) s0[i] = g_h[b * HVEC + i];
    __syncthreads();

    if (tid < H1_DIM) {
        float a = b1[tid];
        for (int i = 0; i < HVEC; ++i) a += s0[i] * w1[i * H1_DIM + tid];
        s1[tid] = sigmoidf_(a);
    }
    __syncthreads();

    if (tid < H2_DIM) {
        float a = b2[tid];
        for (int i = 0; i < H1_DIM; ++i) a += s1[i] * w2[i * H2_DIM + tid];
        s2[tid] = sigmoidf_(a);
    }
    __syncthreads();

    if (tid < 2) {
        float a = b3[tid];
        for (int i = 0; i < H2_DIM; ++i) a += s2[i] * w3[i * 2 + tid];
        out[b * 2 + tid] = a;
    }
}

// ---------------------------------------------------------------------------
extern "C" void kernel_launch(void* const* d_in, const int* in_sizes, int n_in,
                              void* d_out, int out_size) {
    const float* x      = (const float*)d_in[0];
    const float* conv_w = (const float*)d_in[1];
    const float* conv_b = (const float*)d_in[2];
    const float* w1     = (const float*)d_in[3];
    const float* b1     = (const float*)d_in[4];
    const float* w2     = (const float*)d_in[5];
    const float* b2     = (const float*)d_in[6];
    const float* w3     = (const float*)d_in[7];
    const float* b3     = (const float*)d_in[8];
    float* out = (float*)d_out;

    dim3 g1((N_DIM + NTILE - 1) / NTILE, B_DIM, FCHUNKS); // 20 x 8 x 8
    k_conv<<<g1, 256>>>(x, conv_w);
    k_minmax<<<B_DIM * J_DIM, 256>>>(conv_b);
    k_mlp<<<B_DIM, 256>>>(w1, b1, w2, b2, w3, b3, out);
}

// round 14
// speedup vs baseline: 1.4647x; 1.4647x over previous
#include <cuda_runtime.h>
#include <math.h>

#define F_DIM   2048
#define N_DIM   10000
#define B_DIM   8
#define J_DIM   10
#define R_DIM   20
#define H1_DIM  200
#define H2_DIM  100
#define FCHUNKS 8
#define FCHUNK  256                 /* F_DIM / FCHUNKS */
#define NTILE   512                 /* n per CTA: 128 threads * 4 */
#define FB      16                  /* f-rows per pipeline stage */
#define NSTAGE  (FCHUNK / FB)       /* 16 stages */
#define HVEC    (2 * R_DIM * J_DIM) /* 400 */
#define SMEM_W  (FCHUNK * J_DIM * 8)          /* 20480 B splatted weights */
#define SMEM_X  (2 * FB * NTILE * 4)          /* 65536 B x double buffer */
#define SMEM_CONV (SMEM_W + SMEM_X)           /* 86016 B */

// Scratch (static device globals -- no allocation allowed)
__device__ float g_part[FCHUNKS * B_DIM * J_DIM * N_DIM]; // 25.6 MB partial sums
__device__ float g_h[B_DIM * HVEC];                       // [8][400] MLP input

__device__ __forceinline__ void fma2(unsigned long long &acc,
                                     unsigned long long a,
                                     unsigned long long b) {
    // packed 2x fp32 FMA (FFMA2) -- only reachable via PTX f32x2
    asm("fma.rn.f32x2 %0, %1, %2, %0;" : "+l"(acc) : "l"(a), "l"(b));
}

__device__ __forceinline__ void cp16(unsigned dst_smem, const float* src) {
    asm volatile("cp.async.cg.shared.global [%0], [%1], 16;"
                 :: "r"(dst_smem), "l"(src));
}

// ---------------------------------------------------------------------------
// Kernel 1: streaming skinny GEMM, cp.async double-buffered.
// Thread: one b, 4 consecutive n, one F-chunk of 256. Stage = 16 f-rows x
// 512 n (32 KB) prefetched into smem while the previous stage is consumed.
// Consumer per f-row: 1 LDS.128 (x, 4 phases) + 5 LDS.128 (splatted weights,
// broadcast) + 20 FFMA2. No LDG in the consumer -> no long-scoreboard stalls.
// ---------------------------------------------------------------------------
__global__ __launch_bounds__(128) void k_conv(const float* __restrict__ x,
                                              const float* __restrict__ conv_w) {
    extern __shared__ __align__(16) char smem_raw[];
    unsigned long long* wsp = reinterpret_cast<unsigned long long*>(smem_raw);
    float*              xs  = reinterpret_cast<float*>(smem_raw + SMEM_W);

    const int tid   = threadIdx.x;
    const int b     = blockIdx.y;
    const int fc    = blockIdx.z;
    const int fbase = fc * FCHUNK;

    // One-time weight load + splat: wsp[fl*10 + j] = {w[j][fbase+fl], same}
    for (int idx = tid; idx < FCHUNK * J_DIM; idx += 128) {
        const int fl = idx / J_DIM, j = idx % J_DIM;
        const float w = conv_w[j * F_DIM + fbase + fl];
        float2 ww = make_float2(w, w);
        wsp[idx] = *reinterpret_cast<unsigned long long*>(&ww);
    }
    // visibility covered by the stage-0 __syncthreads below

    const int  n0    = blockIdx.x * NTILE + tid * 4;
    const bool valid = (n0 < N_DIM);   // per-thread all-or-nothing (272 = 68*4)

    const float*   xbase  = x + (size_t)(b * F_DIM + fbase) * N_DIM + n0;
    const unsigned xs_u32 = (unsigned)__cvta_generic_to_shared(xs);

    unsigned long long acc[2 * J_DIM];
#pragma unroll
    for (int i = 0; i < 2 * J_DIM; ++i) acc[i] = 0ull;

    // prologue: stage 0
    if (valid) {
#pragma unroll
        for (int r = 0; r < FB; ++r)
            cp16(xs_u32 + r * (NTILE * 4) + tid * 16, xbase + (size_t)r * N_DIM);
    }
    asm volatile("cp.async.commit_group;");

    for (int s = 0; s < NSTAGE; ++s) {
        if (s + 1 < NSTAGE) {
            const int buf = (s + 1) & 1;
            if (valid) {
#pragma unroll
                for (int r = 0; r < FB; ++r)
                    cp16(xs_u32 + buf * (FB * NTILE * 4) + r * (NTILE * 4) + tid * 16,
                         xbase + (size_t)((s + 1) * FB + r) * N_DIM);
            }
            asm volatile("cp.async.commit_group;");
            asm volatile("cp.async.wait_group 1;");   // stage s complete
        } else {
            asm volatile("cp.async.wait_group 0;");
        }
        __syncthreads();

        if (valid) {
            const float* xbuf = xs + (s & 1) * (FB * NTILE);
            const unsigned long long* wrow = &wsp[(size_t)s * FB * J_DIM];
#pragma unroll
            for (int r = 0; r < FB; ++r) {
                const ulonglong2 xv =
                    *reinterpret_cast<const ulonglong2*>(xbuf + r * NTILE + tid * 4);
                const ulonglong2* wp =
                    reinterpret_cast<const ulonglong2*>(wrow + r * J_DIM);
#pragma unroll
                for (int jj = 0; jj < 5; ++jj) {      // 2 j per LDS.128
                    const ulonglong2 w2 = wp[jj];
                    fma2(acc[4 * jj + 0], xv.x, w2.x);
                    fma2(acc[4 * jj + 1], xv.y, w2.x);
                    fma2(acc[4 * jj + 2], xv.x, w2.y);
                    fma2(acc[4 * jj + 3], xv.y, w2.y);
                }
            }
        }
        __syncthreads();   // all readers done with buf s&1 before it is refilled
    }

    if (valid) {
        float* pout = g_part + (size_t)(fc * B_DIM * J_DIM + b * J_DIM) * N_DIM + n0;
#pragma unroll
        for (int jj = 0; jj < 5; ++jj) {
            ulonglong2 v0; v0.x = acc[4 * jj + 0]; v0.y = acc[4 * jj + 1];
            *reinterpret_cast<ulonglong2*>(pout + (size_t)(2 * jj) * N_DIM) = v0;
            ulonglong2 v1; v1.x = acc[4 * jj + 2]; v1.y = acc[4 * jj + 3];
            *reinterpret_cast<ulonglong2*>(pout + (size_t)(2 * jj + 1) * N_DIM) = v1;
        }
    }
}

// ---------------------------------------------------------------------------
// Kernel 2: per (b,j) row. One pass sums partials into smem AND records each
// thread's local max & min (tournament leaves). Each extraction pass then
// only (a) reduces the 256 leaf entries with warp 0, (b) rescans the single
// victim thread's ~40 elements. Max phase removes with -INF (recording
// idx/val), restore, then min phase (initial lmin stays valid after exact
// restore). Bias added post-selection (uniform shift, selection-invariant).
// ---------------------------------------------------------------------------
__global__ __launch_bounds__(256) void k_minmax(const float* __restrict__ conv_b) {
    const int row = blockIdx.x;            // b*10 + j
    const int tid = threadIdx.x;
    __shared__ float vals[N_DIM];          // 40 KB
    __shared__ float lmax[256], lmin[256];
    __shared__ int   lamax[256], lamin[256];
    __shared__ int   s_victim;
    __shared__ int   rem_idx[R_DIM];
    __shared__ float rem_val[R_DIM];

    float lm = -INFINITY, ln = INFINITY;
    int   la = tid, li = tid;
    for (int n = tid; n < N_DIM; n += 256) {
        float s = 0.f;
#pragma unroll
        for (int fcc = 0; fcc < FCHUNKS; ++fcc)
            s += g_part[(fcc * B_DIM * J_DIM + row) * N_DIM + n];
        vals[n] = s;
        if (s > lm) { lm = s; la = n; }
        if (s < ln) { ln = s; li = n; }
    }
    lmax[tid] = lm; lamax[tid] = la;
    lmin[tid] = ln; lamin[tid] = li;
    __syncthreads();

    const int   lane = tid & 31;
    const int   j    = row % J_DIM;
    const float bias = conv_b[j];
    float* out = g_h + (row / J_DIM) * HVEC + j * (2 * R_DIM);

    // ---- Phase A: top-R descending ----
    for (int pass = 0; pass < R_DIM; ++pass) {
        if (tid < 32) {
            float m = -INFINITY; int owner = 0;
#pragma unroll
            for (int k = lane; k < 256; k += 32)
                if (lmax[k] > m) { m = lmax[k]; owner = k; }
#pragma unroll
            for (int off = 16; off > 0; off >>= 1) {
                float o  = __shfl_down_sync(0xffffffffu, m, off);
                int   oo = __shfl_down_sync(0xffffffffu, owner, off);
                if (o > m) { m = o; owner = oo; }
            }
            if (lane == 0) {
                const int idx = lamax[owner];
                out[pass]     = m + bias;      // pass-th largest, descending
                rem_idx[pass] = idx;
                rem_val[pass] = m;
                vals[idx]     = -INFINITY;
                s_victim      = owner;
            }
        }
        __syncthreads();
        if (tid == s_victim) {                 // refresh victim leaf only
            float m = -INFINITY; int a = tid;
            for (int n = tid; n < N_DIM; n += 256)
                if (vals[n] > m) { m = vals[n]; a = n; }
            lmax[tid] = m; lamax[tid] = a;
        }
        __syncthreads();
    }

    // exact restore of removed top values; initial lmin remains valid
    if (tid < R_DIM) vals[rem_idx[tid]] = rem_val[tid];
    __syncthreads();

    // ---- Phase B: bottom-R, k-th smallest -> position 2R-1-pass ----
    for (int pass = 0; pass < R_DIM; ++pass) {
        if (tid < 32) {
            float m = INFINITY; int owner = 0;
#pragma unroll
            for (int k = lane; k < 256; k += 32)
                if (lmin[k] < m) { m = lmin[k]; owner = k; }
#pragma unroll
            for (int off = 16; off > 0; off >>= 1) {
                float o  = __shfl_down_sync(0xffffffffu, m, off);
                int   oo = __shfl_down_sync(0xffffffffu, owner, off);
                if (o < m) { m = o; owner = oo; }
            }
            if (lane == 0) {
                const int idx = lamin[owner];
                out[2 * R_DIM - 1 - pass] = m + bias;
                vals[idx] = INFINITY;
                s_victim  = owner;
            }
        }
        __syncthreads();
        if (tid == s_victim) {
            float m = INFINITY; int a = tid;
            for (int n = tid; n < N_DIM; n += 256)
                if (vals[n] < m) { m = vals[n]; a = n; }
            lmin[tid] = m; lamin[tid] = a;
        }
        __syncthreads();
    }
}

// ---------------------------------------------------------------------------
// Kernel 3: tiny MLP, one CTA per batch row.
// ---------------------------------------------------------------------------
__device__ __forceinline__ float sigmoidf_(float z) {
    return 1.f / (1.f + expf(-z));
}

__global__ __launch_bounds__(256) void k_mlp(const float* __restrict__ w1,
                                             const float* __restrict__ b1,
                                             const float* __restrict__ w2,
                                             const float* __restrict__ b2,
                                             const float* __restrict__ w3,
                                             const float* __restrict__ b3,
                                             float* __restrict__ out) {
    const int b   = blockIdx.x;
    const int tid = threadIdx.x;
    __shared__ float s0[HVEC], s1[H1_DIM], s2[H2_DIM];

    for (int i = tid; i < HVEC; i += 256) s0[i] = g_h[b * HVEC + i];
    __syncthreads();

    if (tid < H1_DIM) {
        float a = b1[tid];
        for (int i = 0; i < HVEC; ++i) a += s0[i] * w1[i * H1_DIM + tid];
        s1[tid] = sigmoidf_(a);
    }
    __syncthreads();

    if (tid < H2_DIM) {
        float a = b2[tid];
        for (int i = 0; i < H1_DIM; ++i) a += s1[i] * w2[i * H2_DIM + tid];
        s2[tid] = sigmoidf_(a);
    }
    __syncthreads();

    if (tid < 2) {
        float a = b3[tid];
        for (int i = 0; i < H2_DIM; ++i) a += s2[i] * w3[i * 2 + tid];
        out[b * 2 + tid] = a;
    }
}

// ---------------------------------------------------------------------------
extern "C" void kernel_launch(void* const* d_in, const int* in_sizes, int n_in,
                              void* d_out, int out_size) {
    const float* x      = (const float*)d_in[0];
    const float* conv_w = (const float*)d_in[1];
    const float* conv_b = (const float*)d_in[2];
    const float* w1     = (const float*)d_in[3];
    const float* b1     = (const float*)d_in[4];
    const float* w2     = (const float*)d_in[5];
    const float* b2     = (const float*)d_in[6];
    const float* w3     = (const float*)d_in[7];
    const float* b3     = (const float*)d_in[8];
    float* out = (float*)d_out;

    // 84 KB dynamic smem (> 48 KB static limit); idempotent, capture-safe
    cudaFuncSetAttribute(k_conv, cudaFuncAttributeMaxDynamicSharedMemorySize,
                         SMEM_CONV);

    dim3 g1((N_DIM + NTILE - 1) / NTILE, B_DIM, FCHUNKS); // 20 x 8 x 8
    k_conv<<<g1, 128, SMEM_CONV>>>(x, conv_w);
    k_minmax<<<B_DIM * J_DIM, 256>>>(conv_b);
    k_mlp<<<B_DIM, 256>>>(w1, b1, w2, b2, w3, b3, out);
}

// round 17
// speedup vs baseline: 1.5192x; 1.0372x over previous
#include <cuda_runtime.h>
#include <math.h>

#define F_DIM   2048
#define N_DIM   10000
#define B_DIM   8
#define J_DIM   10
#define R_DIM   20
#define H1_DIM  200
#define H2_DIM  100
#define FCHUNKS 8
#define FCHUNK  256                 /* F_DIM / FCHUNKS */
#define NTILE   512                 /* n per CTA: 128 threads * 4 */
#define FB      8                   /* f-rows per pipeline stage */
#define NSTAGE  (FCHUNK / FB)       /* 32 stages */
#define HVEC    (2 * R_DIM * J_DIM) /* 400 */
#define SMEM_W  (FCHUNK * J_DIM * 8)          /* 20480 B splatted weights */
#define SMEM_X  (2 * FB * NTILE * 4)          /* 32768 B x double buffer */
#define SMEM_CONV (SMEM_W + SMEM_X)           /* 53248 B -> 4 CTAs/SM */
#define SEG     (N_DIM / 8)         /* 1250 elements per warp in k_minmax */

// Scratch (static device globals -- no allocation allowed)
__device__ float g_part[FCHUNKS * B_DIM * J_DIM * N_DIM]; // 25.6 MB partial sums
__device__ float g_h[B_DIM * HVEC];                       // [8][400] MLP input

__device__ __forceinline__ void fma2(unsigned long long &acc,
                                     unsigned long long a,
                                     unsigned long long b) {
    // packed 2x fp32 FMA (FFMA2) -- only reachable via PTX f32x2
    asm("fma.rn.f32x2 %0, %1, %2, %0;" : "+l"(acc) : "l"(a), "l"(b));
}

__device__ __forceinline__ void cp16(unsigned dst_smem, const float* src) {
    asm volatile("cp.async.cg.shared.global [%0], [%1], 16;"
                 :: "r"(dst_smem), "l"(src));
}

// ---------------------------------------------------------------------------
// Kernel 1: streaming skinny GEMM, cp.async double-buffered.
// Thread: one b, 4 consecutive n, one F-chunk of 256. Stage = 8 f-rows x
// 512 n (16 KB) prefetched into smem while the previous stage is consumed.
// 52 KB smem -> 4 CTAs/SM (16 warps) to hide per-stage barrier skew.
// ---------------------------------------------------------------------------
__global__ __launch_bounds__(128) void k_conv(const float* __restrict__ x,
                                              const float* __restrict__ conv_w) {
    extern __shared__ __align__(16) char smem_raw[];
    unsigned long long* wsp = reinterpret_cast<unsigned long long*>(smem_raw);
    float*              xs  = reinterpret_cast<float*>(smem_raw + SMEM_W);

    const int tid   = threadIdx.x;
    const int b     = blockIdx.y;
    const int fc    = blockIdx.z;
    const int fbase = fc * FCHUNK;

    // One-time weight load + splat: wsp[fl*10 + j] = {w[j][fbase+fl], same}
    for (int idx = tid; idx < FCHUNK * J_DIM; idx += 128) {
        const int fl = idx / J_DIM, j = idx % J_DIM;
        const float w = conv_w[j * F_DIM + fbase + fl];
        float2 ww = make_float2(w, w);
        wsp[idx] = *reinterpret_cast<unsigned long long*>(&ww);
    }
    // visibility covered by the stage-0 __syncthreads below

    const int  n0    = blockIdx.x * NTILE + tid * 4;
    const bool valid = (n0 < N_DIM);   // per-thread all-or-nothing (272 = 68*4)

    const float*   xbase  = x + (size_t)(b * F_DIM + fbase) * N_DIM + n0;
    const unsigned xs_u32 = (unsigned)__cvta_generic_to_shared(xs);

    unsigned long long acc[2 * J_DIM];
#pragma unroll
    for (int i = 0; i < 2 * J_DIM; ++i) acc[i] = 0ull;

    // prologue: stage 0
    if (valid) {
#pragma unroll
        for (int r = 0; r < FB; ++r)
            cp16(xs_u32 + r * (NTILE * 4) + tid * 16, xbase + (size_t)r * N_DIM);
    }
    asm volatile("cp.async.commit_group;");

    for (int s = 0; s < NSTAGE; ++s) {
        if (s + 1 < NSTAGE) {
            const int buf = (s + 1) & 1;
            if (valid) {
#pragma unroll
                for (int r = 0; r < FB; ++r)
                    cp16(xs_u32 + buf * (FB * NTILE * 4) + r * (NTILE * 4) + tid * 16,
                         xbase + (size_t)((s + 1) * FB + r) * N_DIM);
            }
            asm volatile("cp.async.commit_group;");
            asm volatile("cp.async.wait_group 1;");   // stage s complete
        } else {
            asm volatile("cp.async.wait_group 0;");
        }
        __syncthreads();

        if (valid) {
            const float* xbuf = xs + (s & 1) * (FB * NTILE);
            const unsigned long long* wrow = &wsp[(size_t)s * FB * J_DIM];
#pragma unroll
            for (int r = 0; r < FB; ++r) {
                const ulonglong2 xv =
                    *reinterpret_cast<const ulonglong2*>(xbuf + r * NTILE + tid * 4);
                const ulonglong2* wp =
                    reinterpret_cast<const ulonglong2*>(wrow + r * J_DIM);
#pragma unroll
                for (int jj = 0; jj < 5; ++jj) {      // 2 j per LDS.128
                    const ulonglong2 w2 = wp[jj];
                    fma2(acc[4 * jj + 0], xv.x, w2.x);
                    fma2(acc[4 * jj + 1], xv.y, w2.x);
                    fma2(acc[4 * jj + 2], xv.x, w2.y);
                    fma2(acc[4 * jj + 3], xv.y, w2.y);
                }
            }
        }
        __syncthreads();   // all readers done with buf s&1 before it is refilled
    }

    if (valid) {
        float* pout = g_part + (size_t)(fc * B_DIM * J_DIM + b * J_DIM) * N_DIM + n0;
#pragma unroll
        for (int jj = 0; jj < 5; ++jj) {
            ulonglong2 v0; v0.x = acc[4 * jj + 0]; v0.y = acc[4 * jj + 1];
            *reinterpret_cast<ulonglong2*>(pout + (size_t)(2 * jj) * N_DIM) = v0;
            ulonglong2 v1; v1.x = acc[4 * jj + 2]; v1.y = acc[4 * jj + 3];
            *reinterpret_cast<ulonglong2*>(pout + (size_t)(2 * jj + 1) * N_DIM) = v1;
        }
    }
}

// ---------------------------------------------------------------------------
// Kernel 2: per (b,j) row, barrier-free warp-segment tournament.
// 8 warps x 1250-element segments. Each warp extracts its own top-20 and
// bottom-20 with shfl butterflies (deterministic idx tie-break -> all lanes
// agree) + owner-lane rescan. No CTA barriers inside the passes. Warp 0 then
// merges the 160 top candidates while warp 1 merges the 160 bottom
// candidates, fully in registers (5 candidates/lane).
// Bias added at merge output (uniform shift, selection-invariant).
// ---------------------------------------------------------------------------
__global__ __launch_bounds__(256) void k_minmax(const float* __restrict__ conv_b) {
    const int row = blockIdx.x;            // b*10 + j
    const int tid = threadIdx.x;
    __shared__ float vals[N_DIM];          // 40 KB
    __shared__ float cand_top[8 * R_DIM], cand_bot[8 * R_DIM];
    __shared__ int   rem_i[8 * R_DIM];

    // sum partials
    for (int n = tid; n < N_DIM; n += 256) {
        float s = 0.f;
#pragma unroll
        for (int fcc = 0; fcc < FCHUNKS; ++fcc)
            s += g_part[(size_t)(fcc * B_DIM * J_DIM + row) * N_DIM + n];
        vals[n] = s;
    }
    __syncthreads();

    const int w    = tid >> 5, lane = tid & 31;
    const int seg  = w * SEG, seg_end = seg + SEG;

    // initial per-lane scan (max and min leaves)
    float lm = -INFINITY, ln = INFINITY;
    int   li = seg + lane, ni = seg + lane;
    for (int n = seg + lane; n < seg_end; n += 32) {
        const float v = vals[n];
        if (v > lm) { lm = v; li = n; }
        if (v < ln) { ln = v; ni = n; }
    }

    // ---- Phase A: warp-local top-R (descending) ----
    for (int p = 0; p < R_DIM; ++p) {
        float bv = lm; int bi = li;
#pragma unroll
        for (int off = 16; off > 0; off >>= 1) {
            const float ov = __shfl_xor_sync(0xffffffffu, bv, off);
            const int   oi = __shfl_xor_sync(0xffffffffu, bi, off);
            if (ov > bv || (ov == bv && oi < bi)) { bv = ov; bi = oi; }
        }
        if (lane == 0) { cand_top[w * R_DIM + p] = bv; rem_i[w * R_DIM + p] = bi; }
        if (bi == li) {                      // owner lane removes + rescans
            vals[bi] = -INFINITY;
            lm = -INFINITY; li = seg + lane;
            for (int n = seg + lane; n < seg_end; n += 32) {
                const float v = vals[n];
                if (v > lm) { lm = v; li = n; }
            }
        }
    }

    // exact restore of this warp's removed values (min leaves stay valid)
    __syncwarp();
    if (lane < R_DIM) vals[rem_i[w * R_DIM + lane]] = cand_top[w * R_DIM + lane];
    __syncwarp();

    // ---- Phase B: warp-local bottom-R (ascending extraction) ----
    for (int p = 0; p < R_DIM; ++p) {
        float bv = ln; int bi = ni;
#pragma unroll
        for (int off = 16; off > 0; off >>= 1) {
            const float ov = __shfl_xor_sync(0xffffffffu, bv, off);
            const int   oi = __shfl_xor_sync(0xffffffffu, bi, off);
            if (ov < bv || (ov == bv && oi < bi)) { bv = ov; bi = oi; }
        }
        if (lane == 0) cand_bot[w * R_DIM + p] = bv;
        if (bi == ni) {
            vals[bi] = INFINITY;
            ln = INFINITY; ni = seg + lane;
            for (int n = seg + lane; n < seg_end; n += 32) {
                const float v = vals[n];
                if (v < ln) { ln = v; ni = n; }
            }
        }
    }
    __syncthreads();

    // ---- Merge: warp 0 -> top-20 desc, warp 1 -> bottom-20 (concurrent) ----
    const int   j    = row % J_DIM;
    const float bias = conv_b[j];
    float* out = g_h + (row / J_DIM) * HVEC + j * (2 * R_DIM);

    if (w < 2) {
        const bool  is_top = (w == 0);
        const float* cand  = is_top ? cand_top : cand_bot;
        const float sent   = is_top ? -INFINITY : INFINITY;
        float c[5];
#pragma unroll
        for (int k = 0; k < 5; ++k) c[k] = cand[lane * 5 + k];

        // local best
        float lbv; int lbk;
        lbv = c[0]; lbk = 0;
#pragma unroll
        for (int k = 1; k < 5; ++k) {
            const bool better = is_top ? (c[k] > lbv) : (c[k] < lbv);
            if (better) { lbv = c[k]; lbk = k; }
        }

        for (int p = 0; p < R_DIM; ++p) {
            float bv = lbv; int bid = lane * 5 + lbk;
#pragma unroll
            for (int off = 16; off > 0; off >>= 1) {
                const float ov = __shfl_xor_sync(0xffffffffu, bv, off);
                const int   oi = __shfl_xor_sync(0xffffffffu, bid, off);
                const bool better = is_top ? (ov > bv || (ov == bv && oi < bid))
                                           : (ov < bv || (ov == bv && oi < bid));
                if (better) { bv = ov; bid = oi; }
            }
            if (lane == 0) {
                if (is_top) out[p] = bv + bias;                  // desc
                else        out[2 * R_DIM - 1 - p] = bv + bias;  // asc -> tail
            }
            if (bid / 5 == lane) {           // owner invalidates + recomputes
                c[bid % 5] = sent;
                lbv = c[0]; lbk = 0;
#pragma unroll
                for (int k = 1; k < 5; ++k) {
                    const bool better = is_top ? (c[k] > lbv) : (c[k] < lbv);
                    if (better) { lbv = c[k]; lbk = k; }
                }
            }
        }
    }
}

// ---------------------------------------------------------------------------
// Kernel 3: tiny MLP, one CTA per batch row.
// ---------------------------------------------------------------------------
__device__ __forceinline__ float sigmoidf_(float z) {
    return 1.f / (1.f + expf(-z));
}

__global__ __launch_bounds__(256) void k_mlp(const float* __restrict__ w1,
                                             const float* __restrict__ b1,
                                             const float* __restrict__ w2,
                                             const float* __restrict__ b2,
                                             const float* __restrict__ w3,
                                             const float* __restrict__ b3,
                                             float* __restrict__ out) {
    const int b   = blockIdx.x;
    const int tid = threadIdx.x;
    __shared__ float s0[HVEC], s1[H1_DIM], s2[H2_DIM];

    for (int i = tid; i < HVEC; i += 256) s0[i] = g_h[b * HVEC + i];
    __syncthreads();

    if (tid < H1_DIM) {
        float a = b1[tid];
        for (int i = 0; i < HVEC; ++i) a += s0[i] * w1[i * H1_DIM + tid];
        s1[tid] = sigmoidf_(a);
    }
    __syncthreads();

    if (tid < H2_DIM) {
        float a = b2[tid];
        for (int i = 0; i < H1_DIM; ++i) a += s1[i] * w2[i * H2_DIM + tid];
        s2[tid] = sigmoidf_(a);
    }
    __syncthreads();

    if (tid < 2) {
        float a = b3[tid];
        for (int i = 0; i < H2_DIM; ++i) a += s2[i] * w3[i * 2 + tid];
        out[b * 2 + tid] = a;
    }
}

// ---------------------------------------------------------------------------
extern "C" void kernel_launch(void* const* d_in, const int* in_sizes, int n_in,
                              void* d_out, int out_size) {
    const float* x      = (const float*)d_in[0];
    const float* conv_w = (const float*)d_in[1];
    const float* conv_b = (const float*)d_in[2];
    const float* w1     = (const float*)d_in[3];
    const float* b1     = (const float*)d_in[4];
    const float* w2     = (const float*)d_in[5];
    const float* b2     = (const float*)d_in[6];
    const float* w3     = (const float*)d_in[7];
    const float* b3     = (const float*)d_in[8];
    float* out = (float*)d_out;

    // 52 KB dynamic smem (> 48 KB static limit); idempotent, capture-safe
    cudaFuncSetAttribute(k_conv, cudaFuncAttributeMaxDynamicSharedMemorySize,
                         SMEM_CONV);

    dim3 g1((N_DIM + NTILE - 1) / NTILE, B_DIM, FCHUNKS); // 20 x 8 x 8
    k_conv<<<g1, 128, SMEM_CONV>>>(x, conv_w);
    k_minmax<<<B_DIM * J_DIM, 256>>>(conv_b);
    k_mlp<<<B_DIM, 256>>>(w1, b1, w2, b2, w3, b3, out);
}